// round 10
// baseline (speedup 1.0000x reference)
#include <cuda_runtime.h>
#include <stdint.h>
#include <math.h>

// ---------------- problem constants ----------------
#define M_TOTAL 32768
#define KD      1024
#define N_TOTAL 4112
#define SEC_W   1024
#define Q_ELEMS 33554432ULL          // 32768*1024
#define NPAD    4352                 // 17 * 256

// ---------------- GEMM config (R5 champion: 1616.6 us) ----------------
#define BM 128
#define BN 256
#define BK 16
#define STAGES 4
#define NTHREADS 512                  // 16 warps: 2 (M) x 8 (N), warp tile 64x32
#define SA 20                         // smem row stride in floats (pad -> conflict-free)
#define A_ST_FLOATS (BM * SA)         // 2560
#define B_ST_FLOATS (BN * SA)         // 5120
#define STAGE_FLOATS (A_ST_FLOATS + B_ST_FLOATS)   // 7680
#define SMEM_BYTES (STAGES * STAGE_FLOATS * 4)     // 122880

// ---------------- scratch: tf32-rounded fp32 copies ----------------
__device__ float g_Xr[(size_t)M_TOTAL * KD];   // 128 MB
__device__ float g_Wr[(size_t)NPAD * KD];      // 17.8 MB (rows >= 4112 zeroed)

// ---------------- helpers ----------------
__device__ __forceinline__ uint32_t smem_u32(const void* p) {
    uint32_t a;
    asm("{ .reg .u64 t; cvta.to.shared.u64 t, %1; cvt.u32.u64 %0, t; }" : "=r"(a) : "l"(p));
    return a;
}
__device__ __forceinline__ uint32_t f2tf32(float f) {
    uint32_t r;
    asm("cvt.rna.tf32.f32 %0, %1;" : "=r"(r) : "f"(f));
    return r;
}
__device__ __forceinline__ void cp16(uint32_t dst, const float* src) {
    asm volatile("cp.async.cg.shared.global [%0], [%1], 16;" :: "r"(dst), "l"(src) : "memory");
}
#define CP_COMMIT() asm volatile("cp.async.commit_group;" ::: "memory")
#define CP_WAIT2()  asm volatile("cp.async.wait_group 2;" ::: "memory")

__device__ __forceinline__ void ldsm_x4(uint32_t* r, uint32_t addr) {
    asm volatile("ldmatrix.sync.aligned.m8n8.x4.shared.b16 {%0,%1,%2,%3}, [%4];"
        : "=r"(r[0]), "=r"(r[1]), "=r"(r[2]), "=r"(r[3]) : "r"(addr));
}
__device__ __forceinline__ void ldsm_x2(uint32_t* r, uint32_t addr) {
    asm volatile("ldmatrix.sync.aligned.m8n8.x2.shared.b16 {%0,%1}, [%2];"
        : "=r"(r[0]), "=r"(r[1]) : "r"(addr));
}
__device__ __forceinline__ void mma_tf32(float* d, const uint32_t* a, const uint32_t* b) {
    asm volatile(
        "mma.sync.aligned.m16n8k8.row.col.f32.tf32.tf32.f32 "
        "{%0,%1,%2,%3}, {%4,%5,%6,%7}, {%8,%9}, {%0,%1,%2,%3};"
        : "+f"(d[0]), "+f"(d[1]), "+f"(d[2]), "+f"(d[3])
        : "r"(a[0]), "r"(a[1]), "r"(a[2]), "r"(a[3]), "r"(b[0]), "r"(b[1]));
}

// ---------------- tf32 rounding pre-passes ----------------
// X: 4 coalesced float4 chunks per thread (MLP 4, lane-consecutive per instruction)
__global__ __launch_bounds__(256)
void cvt_x_kernel(const float* __restrict__ X)
{
    const size_t base = (size_t)blockIdx.x * (256 * 16) + (size_t)threadIdx.x * 4;
    float4 v[4];
    #pragma unroll
    for (int j = 0; j < 4; ++j)
        v[j] = *(const float4*)(X + base + (size_t)j * 1024);
    #pragma unroll
    for (int j = 0; j < 4; ++j) {
        v[j].x = __uint_as_float(f2tf32(v[j].x));
        v[j].y = __uint_as_float(f2tf32(v[j].y));
        v[j].z = __uint_as_float(f2tf32(v[j].z));
        v[j].w = __uint_as_float(f2tf32(v[j].w));
        *(float4*)(g_Xr + base + (size_t)j * 1024) = v[j];
    }
}

__global__ __launch_bounds__(256)
void cvt_w_kernel(const float* __restrict__ W)
{
    const size_t i = ((size_t)blockIdx.x * 256 + threadIdx.x) * 4;
    const int row = (int)(i >> 10);
    float4 v = make_float4(0.f, 0.f, 0.f, 0.f);
    if (row < N_TOTAL) {
        v = *(const float4*)(W + i);
        v.x = __uint_as_float(f2tf32(v.x));
        v.y = __uint_as_float(f2tf32(v.y));
        v.z = __uint_as_float(f2tf32(v.z));
        v.w = __uint_as_float(f2tf32(v.w));
    }
    *(float4*)(g_Wr + i) = v;
}

// ---------------- fused epilogue store ----------------
__device__ __forceinline__ void store_pair(float* __restrict__ out, size_t r, int gc,
                                           float v0, float v1)
{
    if (gc < 4096) {
        const int sec = gc >> 10;
        float* dst = out + (size_t)sec * Q_ELEMS + r * SEC_W + (gc & 1023);
        if (sec == 3) {                                   // SiLU gate
            v0 = v0 / (1.0f + expf(-v0));
            v1 = v1 / (1.0f + expf(-v1));
        }
        *(float2*)dst = make_float2(v0, v1);
    } else if (gc < N_TOTAL) {                            // sigmoid alpha
        float* dst = out + 4 * Q_ELEMS + r * 16 + (gc - 4096);
        *(float2*)dst = make_float2(1.0f / (1.0f + expf(-v0)),
                                    1.0f / (1.0f + expf(-v1)));
    }
}

// ---------------- main GEMM (tf32 mma.sync + ldmatrix, 4-stage cp.async) ----------------
__global__ __launch_bounds__(NTHREADS, 1)
void gemm_tc_kernel(float* __restrict__ out)
{
    extern __shared__ float sm[];
    const uint32_t smbase = smem_u32(sm);

    const int tid = threadIdx.x;
    const int lane = tid & 31;
    const int wid = tid >> 5;
    const int wm = wid >> 3;           // 0..1  (64 rows each)
    const int wn = wid & 7;            // 0..7  (32 cols each)
    const int g  = lane >> 2;          // groupID
    const int t4 = lane & 3;           // thread-in-group
    const int m0 = blockIdx.y * BM;
    const int n0 = blockIdx.x * BN;

    // ldmatrix per-thread source offsets (in floats, within stage)
    const int a_lrow = wm * 64 + (lane & 7) + ((lane >> 3) & 1) * 8;   // + mi*16
    const int a_lcol = ((lane >> 4) & 1) * 4;                          // + ks*8
    const int t16 = lane & 15;
    const int b_lrow = wn * 32 + (t16 & 7);                            // + ni*8
    const int b_lcol = ((t16 >> 3) & 1) * 4;                           // + ks*8

    float acc[4][4][4];
    #pragma unroll
    for (int mi = 0; mi < 4; ++mi)
        #pragma unroll
        for (int ni = 0; ni < 4; ++ni)
            #pragma unroll
            for (int j = 0; j < 4; ++j) acc[mi][ni][j] = 0.0f;

    // stage loader: 1536 16B chunks (A: 512, B: 1024), 3 per thread
    auto load_stage = [&](int st, int kt) {
        const uint32_t base = smbase + (uint32_t)(st * STAGE_FLOATS * 4);
        #pragma unroll
        for (int i = 0; i < 3; ++i) {
            const int c = tid + i * NTHREADS;
            if (c < 512) {
                const int row = c >> 2, q = c & 3;
                cp16(base + (uint32_t)((row * SA + q * 4) * 4),
                     g_Xr + (size_t)(m0 + row) * KD + kt * BK + q * 4);
            } else {
                const int c2 = c - 512;
                const int row = c2 >> 2, q = c2 & 3;
                cp16(base + (uint32_t)((A_ST_FLOATS + row * SA + q * 4) * 4),
                     g_Wr + (size_t)(n0 + row) * KD + kt * BK + q * 4);
            }
        }
    };

    // prologue: prefetch 3 stages
    load_stage(0, 0); CP_COMMIT();
    load_stage(1, 1); CP_COMMIT();
    load_stage(2, 2); CP_COMMIT();
    CP_WAIT2();
    __syncthreads();

    const int NT = KD / BK;   // 64
    #pragma unroll 1
    for (int kt = 0; kt < NT; ++kt) {
        const int st = kt & 3;
        const uint32_t aStage = smbase + (uint32_t)(st * STAGE_FLOATS * 4);
        const uint32_t bStage = aStage + (uint32_t)(A_ST_FLOATS * 4);

        #pragma unroll
        for (int ks = 0; ks < 2; ++ks) {
            uint32_t a[4][4], b[4][2];
            #pragma unroll
            for (int mi = 0; mi < 4; ++mi)
                ldsm_x4(a[mi], aStage +
                    (uint32_t)(((a_lrow + mi * 16) * SA + ks * 8 + a_lcol) * 4));
            #pragma unroll
            for (int ni = 0; ni < 4; ++ni)
                ldsm_x2(b[ni], bStage +
                    (uint32_t)(((b_lrow + ni * 8) * SA + ks * 8 + b_lcol) * 4));
            #pragma unroll
            for (int mi = 0; mi < 4; ++mi)
                #pragma unroll
                for (int ni = 0; ni < 4; ++ni)
                    mma_tf32(acc[mi][ni], a[mi], b[ni]);
        }

        if (kt + 3 < NT) load_stage((kt + 3) & 3, kt + 3);
        CP_COMMIT();
        CP_WAIT2();
        __syncthreads();
    }

    // ---- fused epilogue: direct fragment stores with routing/activations ----
    #pragma unroll
    for (int mi = 0; mi < 4; ++mi) {
        const size_t r0 = (size_t)(m0 + wm * 64 + mi * 16 + g);
        #pragma unroll
        for (int ni = 0; ni < 4; ++ni) {
            const int gc = n0 + wn * 32 + ni * 8 + 2 * t4;
            store_pair(out, r0,     gc, acc[mi][ni][0], acc[mi][ni][1]);
            store_pair(out, r0 + 8, gc, acc[mi][ni][2], acc[mi][ni][3]);
        }
    }
}

// ---------------- pass 2: L2-normalize full 1024-wide K rows ----------------
// One 256-thread block per row; lane-consecutive float4 loads (4 lines/LDG
// instead of 32 -> 8x fewer L1tex wavefronts than the warp-per-row version).
__global__ __launch_bounds__(256)
void knorm_kernel(float* __restrict__ kptr)
{
    __shared__ float warp_ss[8];
    __shared__ float s_scale;

    const int tid = threadIdx.x;
    const int lane = tid & 31;
    float* p = kptr + (size_t)blockIdx.x * SEC_W + tid * 4;

    float4 v = *(const float4*)p;
    float ss = v.x * v.x + v.y * v.y + v.z * v.z + v.w * v.w;
    #pragma unroll
    for (int off = 16; off > 0; off >>= 1)
        ss += __shfl_xor_sync(0xFFFFFFFFu, ss, off);
    if (lane == 0) warp_ss[tid >> 5] = ss;
    __syncthreads();

    if (tid < 32) {
        float s = (lane < 8) ? warp_ss[lane] : 0.0f;
        #pragma unroll
        for (int off = 4; off > 0; off >>= 1)
            s += __shfl_xor_sync(0xFFFFFFFFu, s, off);
        if (lane == 0) s_scale = 1.0f / fmaxf(sqrtf(s), 1e-12f);
    }
    __syncthreads();

    const float sc = s_scale;
    v.x *= sc; v.y *= sc; v.z *= sc; v.w *= sc;
    *(float4*)p = v;
}

extern "C" void kernel_launch(void* const* d_in, const int* in_sizes, int n_in,
                              void* d_out, int out_size)
{
    const float* x = (const float*)d_in[0];   // [4, 8192, 1024] fp32
    const float* W = (const float*)d_in[1];   // [4112, 1024] fp32
    float* out = (float*)d_out;

    cudaFuncSetAttribute(gemm_tc_kernel,
                         cudaFuncAttributeMaxDynamicSharedMemorySize, SMEM_BYTES);

    // 1) round inputs to tf32 (zero-pad W rows to 4352)
    cvt_x_kernel<<<(M_TOTAL * KD / 16) / 256, 256>>>(x);
    cvt_w_kernel<<<(NPAD * KD / 4) / 256, 256>>>(W);

    // 2) tf32 mma.sync GEMM + fused routing/activation epilogue
    dim3 grid(NPAD / BN, M_TOTAL / BM);     // 17 x 256
    gemm_tc_kernel<<<grid, NTHREADS, SMEM_BYTES>>>(out);

    // 3) K row L2-normalization (one block per row)
    knorm_kernel<<<M_TOTAL, 256>>>(out + Q_ELEMS);
}

// round 11
// speedup vs baseline: 1.5307x; 1.5307x over previous
#include <cuda_runtime.h>
#include <stdint.h>
#include <math.h>

// ---------------- problem constants ----------------
#define M_TOTAL 32768
#define KD      1024
#define N_TOTAL 4112
#define SEC_W   1024
#define Q_ELEMS 33554432ULL          // 32768*1024
#define NPAD    4352                 // 17 * 256

// ---------------- GEMM config (R5 champion: 1616.6 us) ----------------
#define BM 128
#define BN 256
#define BK 16
#define STAGES 4
#define NTHREADS 512                  // 16 warps: 2 (M) x 8 (N), warp tile 64x32
#define SA 20                         // smem row stride in floats (pad -> conflict-free)
#define A_ST_FLOATS (BM * SA)         // 2560
#define B_ST_FLOATS (BN * SA)         // 5120
#define STAGE_FLOATS (A_ST_FLOATS + B_ST_FLOATS)   // 7680
#define SMEM_BYTES (STAGES * STAGE_FLOATS * 4)     // 122880

// ---------------- scratch: tf32-rounded fp32 copies ----------------
__device__ float g_Xr[(size_t)M_TOTAL * KD];   // 128 MB
__device__ float g_Wr[(size_t)NPAD * KD];      // 17.8 MB (rows >= 4112 zeroed)

// ---------------- helpers ----------------
__device__ __forceinline__ uint32_t smem_u32(const void* p) {
    uint32_t a;
    asm("{ .reg .u64 t; cvta.to.shared.u64 t, %1; cvt.u32.u64 %0, t; }" : "=r"(a) : "l"(p));
    return a;
}
__device__ __forceinline__ uint32_t f2tf32(float f) {
    uint32_t r;
    asm("cvt.rna.tf32.f32 %0, %1;" : "=r"(r) : "f"(f));
    return r;
}
__device__ __forceinline__ void cp16(uint32_t dst, const float* src) {
    asm volatile("cp.async.cg.shared.global [%0], [%1], 16;" :: "r"(dst), "l"(src) : "memory");
}
#define CP_COMMIT() asm volatile("cp.async.commit_group;" ::: "memory")
#define CP_WAIT2()  asm volatile("cp.async.wait_group 2;" ::: "memory")

__device__ __forceinline__ void ldsm_x4(uint32_t* r, uint32_t addr) {
    asm volatile("ldmatrix.sync.aligned.m8n8.x4.shared.b16 {%0,%1,%2,%3}, [%4];"
        : "=r"(r[0]), "=r"(r[1]), "=r"(r[2]), "=r"(r[3]) : "r"(addr));
}
__device__ __forceinline__ void ldsm_x2(uint32_t* r, uint32_t addr) {
    asm volatile("ldmatrix.sync.aligned.m8n8.x2.shared.b16 {%0,%1}, [%2];"
        : "=r"(r[0]), "=r"(r[1]) : "r"(addr));
}
__device__ __forceinline__ void mma_tf32(float* d, const uint32_t* a, const uint32_t* b) {
    asm volatile(
        "mma.sync.aligned.m16n8k8.row.col.f32.tf32.tf32.f32 "
        "{%0,%1,%2,%3}, {%4,%5,%6,%7}, {%8,%9}, {%0,%1,%2,%3};"
        : "+f"(d[0]), "+f"(d[1]), "+f"(d[2]), "+f"(d[3])
        : "r"(a[0]), "r"(a[1]), "r"(a[2]), "r"(a[3]), "r"(b[0]), "r"(b[1]));
}

// ---------------- tf32 rounding pre-passes (R5-verbatim cvt_x) ----------------
__global__ __launch_bounds__(256)
void cvt_x_kernel(const float* __restrict__ X)
{
    const size_t i = ((size_t)blockIdx.x * 256 + threadIdx.x) * 4;
    float4 v = *(const float4*)(X + i);
    v.x = __uint_as_float(f2tf32(v.x));
    v.y = __uint_as_float(f2tf32(v.y));
    v.z = __uint_as_float(f2tf32(v.z));
    v.w = __uint_as_float(f2tf32(v.w));
    *(float4*)(g_Xr + i) = v;
}

__global__ __launch_bounds__(256)
void cvt_w_kernel(const float* __restrict__ W)
{
    const size_t i = ((size_t)blockIdx.x * 256 + threadIdx.x) * 4;
    const int row = (int)(i >> 10);
    float4 v = make_float4(0.f, 0.f, 0.f, 0.f);
    if (row < N_TOTAL) {
        v = *(const float4*)(W + i);
        v.x = __uint_as_float(f2tf32(v.x));
        v.y = __uint_as_float(f2tf32(v.y));
        v.z = __uint_as_float(f2tf32(v.z));
        v.w = __uint_as_float(f2tf32(v.w));
    }
    *(float4*)(g_Wr + i) = v;
}

// ---------------- fused epilogue store ----------------
__device__ __forceinline__ void store_pair(float* __restrict__ out, size_t r, int gc,
                                           float v0, float v1)
{
    if (gc < 4096) {
        const int sec = gc >> 10;
        float* dst = out + (size_t)sec * Q_ELEMS + r * SEC_W + (gc & 1023);
        if (sec == 3) {                                   // SiLU gate
            v0 = v0 / (1.0f + expf(-v0));
            v1 = v1 / (1.0f + expf(-v1));
        }
        *(float2*)dst = make_float2(v0, v1);
    } else if (gc < N_TOTAL) {                            // sigmoid alpha
        float* dst = out + 4 * Q_ELEMS + r * 16 + (gc - 4096);
        *(float2*)dst = make_float2(1.0f / (1.0f + expf(-v0)),
                                    1.0f / (1.0f + expf(-v1)));
    }
}

// ---------------- main GEMM (tf32 mma.sync + ldmatrix, 4-stage cp.async) ----------------
__global__ __launch_bounds__(NTHREADS, 1)
void gemm_tc_kernel(float* __restrict__ out)
{
    extern __shared__ float sm[];
    const uint32_t smbase = smem_u32(sm);

    const int tid = threadIdx.x;
    const int lane = tid & 31;
    const int wid = tid >> 5;
    const int wm = wid >> 3;           // 0..1  (64 rows each)
    const int wn = wid & 7;            // 0..7  (32 cols each)
    const int g  = lane >> 2;          // groupID
    const int t4 = lane & 3;           // thread-in-group
    const int m0 = blockIdx.y * BM;
    const int n0 = blockIdx.x * BN;

    // ldmatrix per-thread source offsets (in floats, within stage)
    const int a_lrow = wm * 64 + (lane & 7) + ((lane >> 3) & 1) * 8;   // + mi*16
    const int a_lcol = ((lane >> 4) & 1) * 4;                          // + ks*8
    const int t16 = lane & 15;
    const int b_lrow = wn * 32 + (t16 & 7);                            // + ni*8
    const int b_lcol = ((t16 >> 3) & 1) * 4;                           // + ks*8

    float acc[4][4][4];
    #pragma unroll
    for (int mi = 0; mi < 4; ++mi)
        #pragma unroll
        for (int ni = 0; ni < 4; ++ni)
            #pragma unroll
            for (int j = 0; j < 4; ++j) acc[mi][ni][j] = 0.0f;

    // stage loader: 1536 16B chunks (A: 512, B: 1024), 3 per thread
    auto load_stage = [&](int st, int kt) {
        const uint32_t base = smbase + (uint32_t)(st * STAGE_FLOATS * 4);
        #pragma unroll
        for (int i = 0; i < 3; ++i) {
            const int c = tid + i * NTHREADS;
            if (c < 512) {
                const int row = c >> 2, q = c & 3;
                cp16(base + (uint32_t)((row * SA + q * 4) * 4),
                     g_Xr + (size_t)(m0 + row) * KD + kt * BK + q * 4);
            } else {
                const int c2 = c - 512;
                const int row = c2 >> 2, q = c2 & 3;
                cp16(base + (uint32_t)((A_ST_FLOATS + row * SA + q * 4) * 4),
                     g_Wr + (size_t)(n0 + row) * KD + kt * BK + q * 4);
            }
        }
    };

    // prologue: prefetch 3 stages
    load_stage(0, 0); CP_COMMIT();
    load_stage(1, 1); CP_COMMIT();
    load_stage(2, 2); CP_COMMIT();
    CP_WAIT2();
    __syncthreads();

    const int NT = KD / BK;   // 64
    #pragma unroll 1
    for (int kt = 0; kt < NT; ++kt) {
        const int st = kt & 3;
        const uint32_t aStage = smbase + (uint32_t)(st * STAGE_FLOATS * 4);
        const uint32_t bStage = aStage + (uint32_t)(A_ST_FLOATS * 4);

        #pragma unroll
        for (int ks = 0; ks < 2; ++ks) {
            uint32_t a[4][4], b[4][2];
            #pragma unroll
            for (int mi = 0; mi < 4; ++mi)
                ldsm_x4(a[mi], aStage +
                    (uint32_t)(((a_lrow + mi * 16) * SA + ks * 8 + a_lcol) * 4));
            #pragma unroll
            for (int ni = 0; ni < 4; ++ni)
                ldsm_x2(b[ni], bStage +
                    (uint32_t)(((b_lrow + ni * 8) * SA + ks * 8 + b_lcol) * 4));
            #pragma unroll
            for (int mi = 0; mi < 4; ++mi)
                #pragma unroll
                for (int ni = 0; ni < 4; ++ni)
                    mma_tf32(acc[mi][ni], a[mi], b[ni]);
        }

        if (kt + 3 < NT) load_stage((kt + 3) & 3, kt + 3);
        CP_COMMIT();
        CP_WAIT2();
        __syncthreads();
    }

    // ---- fused epilogue: direct fragment stores with routing/activations ----
    #pragma unroll
    for (int mi = 0; mi < 4; ++mi) {
        const size_t r0 = (size_t)(m0 + wm * 64 + mi * 16 + g);
        #pragma unroll
        for (int ni = 0; ni < 4; ++ni) {
            const int gc = n0 + wn * 32 + ni * 8 + 2 * t4;
            store_pair(out, r0,     gc, acc[mi][ni][0], acc[mi][ni][1]);
            store_pair(out, r0 + 8, gc, acc[mi][ni][2], acc[mi][ni][3]);
        }
    }
}

// ---------------- pass 2: L2-normalize full 1024-wide K rows ----------------
// One 256-thread block per row; lane-consecutive float4 loads (4 lines/LDG
// instead of 32 -> 8x fewer L1tex wavefronts; ncu-verified 58.3us vs 67us).
__global__ __launch_bounds__(256)
void knorm_kernel(float* __restrict__ kptr)
{
    __shared__ float warp_ss[8];
    __shared__ float s_scale;

    const int tid = threadIdx.x;
    const int lane = tid & 31;
    float* p = kptr + (size_t)blockIdx.x * SEC_W + tid * 4;

    float4 v = *(const float4*)p;
    float ss = v.x * v.x + v.y * v.y + v.z * v.z + v.w * v.w;
    #pragma unroll
    for (int off = 16; off > 0; off >>= 1)
        ss += __shfl_xor_sync(0xFFFFFFFFu, ss, off);
    if (lane == 0) warp_ss[tid >> 5] = ss;
    __syncthreads();

    if (tid < 32) {
        float s = (lane < 8) ? warp_ss[lane] : 0.0f;
        #pragma unroll
        for (int off = 4; off > 0; off >>= 1)
            s += __shfl_xor_sync(0xFFFFFFFFu, s, off);
        if (lane == 0) s_scale = 1.0f / fmaxf(sqrtf(s), 1e-12f);
    }
    __syncthreads();

    const float sc = s_scale;
    v.x *= sc; v.y *= sc; v.z *= sc; v.w *= sc;
    *(float4*)p = v;
}

extern "C" void kernel_launch(void* const* d_in, const int* in_sizes, int n_in,
                              void* d_out, int out_size)
{
    const float* x = (const float*)d_in[0];   // [4, 8192, 1024] fp32
    const float* W = (const float*)d_in[1];   // [4112, 1024] fp32
    float* out = (float*)d_out;

    cudaFuncSetAttribute(gemm_tc_kernel,
                         cudaFuncAttributeMaxDynamicSharedMemorySize, SMEM_BYTES);

    // 1) round inputs to tf32 (zero-pad W rows to 4352)
    cvt_x_kernel<<<(M_TOTAL * KD / 4) / 256, 256>>>(x);
    cvt_w_kernel<<<(NPAD * KD / 4) / 256, 256>>>(W);

    // 2) tf32 mma.sync GEMM + fused routing/activation epilogue
    dim3 grid(NPAD / BN, M_TOTAL / BM);     // 17 x 256
    gemm_tc_kernel<<<grid, NTHREADS, SMEM_BYTES>>>(out);

    // 3) K row L2-normalization (one block per row)
    knorm_kernel<<<M_TOTAL, 256>>>(out + Q_ELEMS);
}

// round 12
// speedup vs baseline: 1.5723x; 1.0272x over previous
#include <cuda_runtime.h>
#include <stdint.h>
#include <math.h>

// ---------------- problem constants ----------------
#define M_TOTAL 32768
#define KD      1024
#define N_TOTAL 4112
#define SEC_W   1024
#define Q_ELEMS 33554432ULL          // 32768*1024
#define NPAD    4352                 // 17 * 256

// ---------------- GEMM config (R5/R11 champion) ----------------
#define BM 128
#define BN 256
#define BK 16
#define STAGES 4
#define NTHREADS 512                  // 16 warps: 2 (M) x 8 (N), warp tile 64x32
#define SA 20                         // smem row stride in floats (pad -> conflict-free)
#define A_ST_FLOATS (BM * SA)         // 2560
#define B_ST_FLOATS (BN * SA)         // 5120
#define STAGE_FLOATS (A_ST_FLOATS + B_ST_FLOATS)   // 7680
#define SMEM_BYTES (STAGES * STAGE_FLOATS * 4)     // 122880

// Bias compensation: raw-fp32 A operands are truncated (RZ) by the tf32 MMA
// datapath, a systematic (1 - 2^-11) scale on every dot product. Pre-scaling
// W by (1 + 2^-11) cancels the mean; the random part matches RNA-rounding
// variance. (K output is norm-invariant to any scale either way.)
#define W_COMP 1.00048828125f

// ---------------- scratch: tf32-rounded, compensated, zero-padded W ----------------
__device__ float g_Wr[(size_t)NPAD * KD];      // 17.8 MB (rows >= 4112 zeroed)

// ---------------- helpers ----------------
__device__ __forceinline__ uint32_t smem_u32(const void* p) {
    uint32_t a;
    asm("{ .reg .u64 t; cvta.to.shared.u64 t, %1; cvt.u32.u64 %0, t; }" : "=r"(a) : "l"(p));
    return a;
}
__device__ __forceinline__ uint32_t f2tf32(float f) {
    uint32_t r;
    asm("cvt.rna.tf32.f32 %0, %1;" : "=r"(r) : "f"(f));
    return r;
}
__device__ __forceinline__ void cp16(uint32_t dst, const float* src) {
    asm volatile("cp.async.cg.shared.global [%0], [%1], 16;" :: "r"(dst), "l"(src) : "memory");
}
#define CP_COMMIT() asm volatile("cp.async.commit_group;" ::: "memory")
#define CP_WAIT2()  asm volatile("cp.async.wait_group 2;" ::: "memory")

__device__ __forceinline__ void ldsm_x4(uint32_t* r, uint32_t addr) {
    asm volatile("ldmatrix.sync.aligned.m8n8.x4.shared.b16 {%0,%1,%2,%3}, [%4];"
        : "=r"(r[0]), "=r"(r[1]), "=r"(r[2]), "=r"(r[3]) : "r"(addr));
}
__device__ __forceinline__ void ldsm_x2(uint32_t* r, uint32_t addr) {
    asm volatile("ldmatrix.sync.aligned.m8n8.x2.shared.b16 {%0,%1}, [%2];"
        : "=r"(r[0]), "=r"(r[1]) : "r"(addr));
}
__device__ __forceinline__ void mma_tf32(float* d, const uint32_t* a, const uint32_t* b) {
    asm volatile(
        "mma.sync.aligned.m16n8k8.row.col.f32.tf32.tf32.f32 "
        "{%0,%1,%2,%3}, {%4,%5,%6,%7}, {%8,%9}, {%0,%1,%2,%3};"
        : "+f"(d[0]), "+f"(d[1]), "+f"(d[2]), "+f"(d[3])
        : "r"(a[0]), "r"(a[1]), "r"(a[2]), "r"(a[3]), "r"(b[0]), "r"(b[1]));
}

// ---------------- W pre-pass: compensate + tf32 round + zero-pad ----------------
__global__ __launch_bounds__(256)
void cvt_w_kernel(const float* __restrict__ W)
{
    const size_t i = ((size_t)blockIdx.x * 256 + threadIdx.x) * 4;
    const int row = (int)(i >> 10);
    float4 v = make_float4(0.f, 0.f, 0.f, 0.f);
    if (row < N_TOTAL) {
        v = *(const float4*)(W + i);
        v.x = __uint_as_float(f2tf32(v.x * W_COMP));
        v.y = __uint_as_float(f2tf32(v.y * W_COMP));
        v.z = __uint_as_float(f2tf32(v.z * W_COMP));
        v.w = __uint_as_float(f2tf32(v.w * W_COMP));
    }
    *(float4*)(g_Wr + i) = v;
}

// ---------------- fused epilogue store ----------------
__device__ __forceinline__ void store_pair(float* __restrict__ out, size_t r, int gc,
                                           float v0, float v1)
{
    if (gc < 4096) {
        const int sec = gc >> 10;
        float* dst = out + (size_t)sec * Q_ELEMS + r * SEC_W + (gc & 1023);
        if (sec == 3) {                                   // SiLU gate
            v0 = v0 / (1.0f + expf(-v0));
            v1 = v1 / (1.0f + expf(-v1));
        }
        *(float2*)dst = make_float2(v0, v1);
    } else if (gc < N_TOTAL) {                            // sigmoid alpha
        float* dst = out + 4 * Q_ELEMS + r * 16 + (gc - 4096);
        *(float2*)dst = make_float2(1.0f / (1.0f + expf(-v0)),
                                    1.0f / (1.0f + expf(-v1)));
    }
}

// ---------------- main GEMM (tf32 mma.sync + ldmatrix, 4-stage cp.async) ----------------
__global__ __launch_bounds__(NTHREADS, 1)
void gemm_tc_kernel(const float* __restrict__ X, float* __restrict__ out)
{
    extern __shared__ float sm[];
    const uint32_t smbase = smem_u32(sm);

    const int tid = threadIdx.x;
    const int lane = tid & 31;
    const int wid = tid >> 5;
    const int wm = wid >> 3;           // 0..1  (64 rows each)
    const int wn = wid & 7;            // 0..7  (32 cols each)
    const int g  = lane >> 2;          // groupID
    const int t4 = lane & 3;           // thread-in-group
    const int m0 = blockIdx.y * BM;
    const int n0 = blockIdx.x * BN;

    // ldmatrix per-thread source offsets (in floats, within stage)
    const int a_lrow = wm * 64 + (lane & 7) + ((lane >> 3) & 1) * 8;   // + mi*16
    const int a_lcol = ((lane >> 4) & 1) * 4;                          // + ks*8
    const int t16 = lane & 15;
    const int b_lrow = wn * 32 + (t16 & 7);                            // + ni*8
    const int b_lcol = ((t16 >> 3) & 1) * 4;                           // + ks*8

    float acc[4][4][4];
    #pragma unroll
    for (int mi = 0; mi < 4; ++mi)
        #pragma unroll
        for (int ni = 0; ni < 4; ++ni)
            #pragma unroll
            for (int j = 0; j < 4; ++j) acc[mi][ni][j] = 0.0f;

    // stage loader: 1536 16B chunks (A raw fp32 from X: 512, B from g_Wr: 1024)
    auto load_stage = [&](int st, int kt) {
        const uint32_t base = smbase + (uint32_t)(st * STAGE_FLOATS * 4);
        #pragma unroll
        for (int i = 0; i < 3; ++i) {
            const int c = tid + i * NTHREADS;
            if (c < 512) {
                const int row = c >> 2, q = c & 3;
                cp16(base + (uint32_t)((row * SA + q * 4) * 4),
                     X + (size_t)(m0 + row) * KD + kt * BK + q * 4);
            } else {
                const int c2 = c - 512;
                const int row = c2 >> 2, q = c2 & 3;
                cp16(base + (uint32_t)((A_ST_FLOATS + row * SA + q * 4) * 4),
                     g_Wr + (size_t)(n0 + row) * KD + kt * BK + q * 4);
            }
        }
    };

    // prologue: prefetch 3 stages
    load_stage(0, 0); CP_COMMIT();
    load_stage(1, 1); CP_COMMIT();
    load_stage(2, 2); CP_COMMIT();
    CP_WAIT2();
    __syncthreads();

    const int NT = KD / BK;   // 64
    #pragma unroll 1
    for (int kt = 0; kt < NT; ++kt) {
        const int st = kt & 3;
        const uint32_t aStage = smbase + (uint32_t)(st * STAGE_FLOATS * 4);
        const uint32_t bStage = aStage + (uint32_t)(A_ST_FLOATS * 4);

        #pragma unroll
        for (int ks = 0; ks < 2; ++ks) {
            uint32_t a[4][4], b[4][2];
            #pragma unroll
            for (int mi = 0; mi < 4; ++mi)
                ldsm_x4(a[mi], aStage +
                    (uint32_t)(((a_lrow + mi * 16) * SA + ks * 8 + a_lcol) * 4));
            #pragma unroll
            for (int ni = 0; ni < 4; ++ni)
                ldsm_x2(b[ni], bStage +
                    (uint32_t)(((b_lrow + ni * 8) * SA + ks * 8 + b_lcol) * 4));
            #pragma unroll
            for (int mi = 0; mi < 4; ++mi)
                #pragma unroll
                for (int ni = 0; ni < 4; ++ni)
                    mma_tf32(acc[mi][ni], a[mi], b[ni]);
        }

        if (kt + 3 < NT) load_stage((kt + 3) & 3, kt + 3);
        CP_COMMIT();
        CP_WAIT2();
        __syncthreads();
    }

    // ---- fused epilogue: direct fragment stores with routing/activations ----
    #pragma unroll
    for (int mi = 0; mi < 4; ++mi) {
        const size_t r0 = (size_t)(m0 + wm * 64 + mi * 16 + g);
        #pragma unroll
        for (int ni = 0; ni < 4; ++ni) {
            const int gc = n0 + wn * 32 + ni * 8 + 2 * t4;
            store_pair(out, r0,     gc, acc[mi][ni][0], acc[mi][ni][1]);
            store_pair(out, r0 + 8, gc, acc[mi][ni][2], acc[mi][ni][3]);
        }
    }
}

// ---------------- pass 2: L2-normalize full 1024-wide K rows ----------------
// One 256-thread block per row; lane-consecutive float4 loads.
__global__ __launch_bounds__(256)
void knorm_kernel(float* __restrict__ kptr)
{
    __shared__ float warp_ss[8];
    __shared__ float s_scale;

    const int tid = threadIdx.x;
    const int lane = tid & 31;
    float* p = kptr + (size_t)blockIdx.x * SEC_W + tid * 4;

    float4 v = *(const float4*)p;
    float ss = v.x * v.x + v.y * v.y + v.z * v.z + v.w * v.w;
    #pragma unroll
    for (int off = 16; off > 0; off >>= 1)
        ss += __shfl_xor_sync(0xFFFFFFFFu, ss, off);
    if (lane == 0) warp_ss[tid >> 5] = ss;
    __syncthreads();

    if (tid < 32) {
        float s = (lane < 8) ? warp_ss[lane] : 0.0f;
        #pragma unroll
        for (int off = 4; off > 0; off >>= 1)
            s += __shfl_xor_sync(0xFFFFFFFFu, s, off);
        if (lane == 0) s_scale = 1.0f / fmaxf(sqrtf(s), 1e-12f);
    }
    __syncthreads();

    const float sc = s_scale;
    v.x *= sc; v.y *= sc; v.z *= sc; v.w *= sc;
    *(float4*)p = v;
}

extern "C" void kernel_launch(void* const* d_in, const int* in_sizes, int n_in,
                              void* d_out, int out_size)
{
    const float* x = (const float*)d_in[0];   // [4, 8192, 1024] fp32
    const float* W = (const float*)d_in[1];   // [4112, 1024] fp32
    float* out = (float*)d_out;

    cudaFuncSetAttribute(gemm_tc_kernel,
                         cudaFuncAttributeMaxDynamicSharedMemorySize, SMEM_BYTES);

    // 1) compensate + round W to tf32, zero-pad rows to NPAD (X is fed raw;
    //    HW truncation bias cancelled by W_COMP)
    cvt_w_kernel<<<(NPAD * KD / 4) / 256, 256>>>(W);

    // 2) tf32 mma.sync GEMM + fused routing/activation epilogue
    dim3 grid(NPAD / BN, M_TOTAL / BM);     // 17 x 256
    gemm_tc_kernel<<<grid, NTHREADS, SMEM_BYTES>>>(x, out);

    // 3) K row L2-normalization (one block per row)
    knorm_kernel<<<M_TOTAL, 256>>>(out + Q_ELEMS);
}